// round 17
// baseline (speedup 1.0000x reference)
#include <cuda_runtime.h>
#include <cstdint>

#define NE       64
#define ND       1024
#define NTOK     65536
#define TILE_M   128
#define KC       64
#define KH       16
#define NCHUNK   (ND / KC)       // 16
#define NTHREADS 288             // 8 consumer warps + 1 producer warp

// ---- dynamic smem layout (float indices), padded-linear ----
#define ROWA        132
#define ROWW        68
#define A_STAGEF    (KC * ROWA)              // 8448
#define W_BASE      (2 * A_STAGEF)           // 16896
#define W_STAGEF    (KC * ROWW)              // 4352
#define SMEM_FLOATS (W_BASE + 2 * W_STAGEF)  // 25600 floats = 102400 B

// named barriers:
//  FULL per (buf, warp-pair): ids 1..8, count 96  (producer 32 + pair 64)
//  EMPTY per buf:             ids 9..10, count 288
//  JOINC (all consumers):     id 11, count 256
//  JOINA (group A only):      id 12, count 128
#define BAR_SYNC(id, cnt)                                                      \
    asm volatile("bar.sync %0, %1;" :: "r"(id), "r"(cnt) : "memory")
#define BAR_ARRIVE(id, cnt)                                                    \
    asm volatile("bar.arrive %0, %1;" :: "r"(id), "r"(cnt) : "memory")
#define FULLB(buf, p) (1 + (buf) * 4 + (p))
#define EMPTYB(buf)   (9 + (buf))
#define JOINC 11
#define JOINA 12

__device__ __forceinline__ void fma2(unsigned long long& acc,
                                     unsigned long long a,
                                     unsigned long long b) {
    asm("fma.rn.f32x2 %0, %1, %2, %0;" : "+l"(acc) : "l"(a), "l"(b));
}
__device__ __forceinline__ unsigned long long addf2(unsigned long long a,
                                                    unsigned long long b) {
    unsigned long long r;
    asm("add.rn.f32x2 %0, %1, %2;" : "=l"(r) : "l"(a), "l"(b));
    return r;
}
__device__ __forceinline__ unsigned long long packdup(float f) {
    unsigned long long d;
    const uint32_t u = __float_as_uint(f);
    asm("mov.b64 %0, {%1, %1};" : "=l"(d) : "r"(u));
    return d;
}

__global__ __launch_bounds__(NTHREADS, 2)
void router_ffma2_kernel(const float* __restrict__ tokens,
                         const int* __restrict__ t_arr,
                         const float* __restrict__ Wg,
                         const float* __restrict__ bg,
                         float* __restrict__ out)
{
    extern __shared__ __align__(16) float smem[];

    const int tid = threadIdx.x;
    const int wid = tid >> 5;
    const int bm  = blockIdx.x * TILE_M;

    if (wid == 8) {
        // ======================= producer warp =======================
        const int lane = tid & 31;
        float4 pa[4][4], pw[4][2];

        for (int ch = 0; ch < NCHUNK; ch++) {
            const int buf = ch & 1;
            if (ch >= 2) BAR_SYNC(EMPTYB(buf), 288);

#pragma unroll
            for (int b = 0; b < 4; b++) {
                const int kh = ch * KC + b * KH;
                // ---- load one 16-k batch ----
#pragma unroll
                for (int rr = 0; rr < 4; rr++) {
#pragma unroll
                    for (int i = 0; i < 4; i++) {
                        const int j = (lane + 32 * rr) + 128 * i;
                        const int m = j >> 2, q = j & 3;
                        pa[rr][i] = *reinterpret_cast<const float4*>(
                            tokens + (size_t)(bm + m) * ND + kh + 4 * q);
                    }
#pragma unroll
                    for (int i = 0; i < 2; i++) {
                        const int j = (lane + 32 * rr) + 128 * i;
                        const int e = j >> 2, q = j & 3;
                        pw[rr][i] = *reinterpret_cast<const float4*>(
                            Wg + (size_t)e * ND + kh + 4 * q);
                    }
                }
                // ---- transpose-store the batch ----
                float* sa = smem + buf * A_STAGEF + b * KH * ROWA;
                float* sw = smem + W_BASE + buf * W_STAGEF + b * KH * ROWW;
#pragma unroll
                for (int rr = 0; rr < 4; rr++) {
#pragma unroll
                    for (int i = 0; i < 4; i++) {
                        const int j = (lane + 32 * rr) + 128 * i;
                        const int m = j >> 2, q = j & 3;
                        const float v[4] = {pa[rr][i].x, pa[rr][i].y,
                                            pa[rr][i].z, pa[rr][i].w};
#pragma unroll
                        for (int r = 0; r < 4; r++)
                            sa[(4 * q + r) * ROWA + m] = v[r];
                    }
#pragma unroll
                    for (int i = 0; i < 2; i++) {
                        const int j = (lane + 32 * rr) + 128 * i;
                        const int e = j >> 2, q = j & 3;
                        const float v[4] = {pw[rr][i].x, pw[rr][i].y,
                                            pw[rr][i].z, pw[rr][i].w};
#pragma unroll
                        for (int r = 0; r < 4; r++)
                            sw[(4 * q + r) * ROWW + e] = v[r];
                    }
                }
            }
            __threadfence_block();
            BAR_ARRIVE(FULLB(buf, 0), 96);
            BAR_ARRIVE(FULLB(buf, 1), 96);
            BAR_ARRIVE(FULLB(buf, 2), 96);
            BAR_ARRIVE(FULLB(buf, 3), 96);
        }
        // producer done; consumers finish on their own barriers
    } else {
        // ======================= consumer warps =======================
        const int tg   = tid & 15;         // tokens {4tg..4tg+3, 64+4tg..+3}
        const int eg   = (tid >> 4) & 7;   // experts 8eg..8eg+7
        const int grp  = tid >> 7;         // 0: k 0..31, 1: k 32..63 per chunk
        const int pair = wid >> 1;         // 0..3
        const int kb0  = grp * 32;

        unsigned long long acc[4][8];
#pragma unroll
        for (int e = 0; e < 8; e++) {
            const unsigned long long b2 =
                grp == 0 ? packdup(__ldg(&bg[8 * eg + e])) : 0ull;
#pragma unroll
            for (int tp = 0; tp < 4; tp++) acc[tp][e] = b2;
        }

        const float* saT = smem + 4 * tg;
        const float* swT = smem + W_BASE + 8 * eg;

#define COMPUTE16(buf, kb)                                                     \
    {                                                                          \
        const float* sa = saT + (buf) * A_STAGEF + (kb) * ROWA;                \
        const float* sw = swT + (buf) * W_STAGEF + (kb) * ROWW;                \
        ulonglong2 A0c = *reinterpret_cast<const ulonglong2*>(sa);             \
        ulonglong2 A1c = *reinterpret_cast<const ulonglong2*>(sa + 64);        \
        float4     w0c = *reinterpret_cast<const float4*>(sw);                 \
        float4     w1c = *reinterpret_cast<const float4*>(sw + 4);             \
        _Pragma("unroll")                                                      \
        for (int k = 0; k < KH; k++) {                                         \
            ulonglong2 A0n, A1n;                                               \
            float4 w0n, w1n;                                                   \
            if (k + 1 < KH) {                                                  \
                A0n = *reinterpret_cast<const ulonglong2*>(                    \
                    sa + (k + 1) * ROWA);                                      \
                A1n = *reinterpret_cast<const ulonglong2*>(                    \
                    sa + (k + 1) * ROWA + 64);                                 \
                w0n = *reinterpret_cast<const float4*>(sw + (k + 1) * ROWW);   \
                w1n = *reinterpret_cast<const float4*>(                        \
                    sw + (k + 1) * ROWW + 4);                                  \
            }                                                                  \
            const unsigned long long a64[4] = {A0c.x, A0c.y, A1c.x, A1c.y};    \
            const unsigned long long wd[8] = {                                 \
                packdup(w0c.x), packdup(w0c.y), packdup(w0c.z),                \
                packdup(w0c.w), packdup(w1c.x), packdup(w1c.y),                \
                packdup(w1c.z), packdup(w1c.w)};                               \
            _Pragma("unroll")                                                  \
            for (int tp = 0; tp < 4; tp++)                                     \
                _Pragma("unroll")                                              \
                for (int e = 0; e < 8; e++) fma2(acc[tp][e], a64[tp], wd[e]);  \
            if (k + 1 < KH) { A0c = A0n; A1c = A1n; w0c = w0n; w1c = w1n; }    \
        }                                                                      \
    }

        for (int ch = 0; ch < NCHUNK; ch++) {
            const int buf = ch & 1;
            BAR_SYNC(FULLB(buf, pair), 96);
            COMPUTE16(buf, kb0);
            COMPUTE16(buf, kb0 + 16);
            BAR_ARRIVE(EMPTYB(buf), 288);
        }

        // ---- split-K reduction: group B dumps, group A adds ----
        // dump sits at smem[0..8191] floats = buf0 A-stage; chunk-15 readers
        // only touch buf1 regions, so no overlap. Transposed layout: index
        // (tp*8+e)*128 + t  -> conflict-free STS/LDS.
        unsigned long long* dump = reinterpret_cast<unsigned long long*>(smem);
        if (grp == 1) {
            const int t = tid - 128;
#pragma unroll
            for (int tp = 0; tp < 4; tp++)
#pragma unroll
                for (int e = 0; e < 8; e++)
                    dump[(tp * 8 + e) * 128 + t] = acc[tp][e];
        }
        BAR_SYNC(JOINC, 256);

        if (grp == 0) {
#pragma unroll
            for (int tp = 0; tp < 4; tp++)
#pragma unroll
                for (int e = 0; e < 8; e++)
                    acc[tp][e] = addf2(acc[tp][e],
                                       dump[(tp * 8 + e) * 128 + tid]);
            BAR_SYNC(JOINA, 128);   // everyone done reading dump

            // ---- scatter acc -> swizzled logits overlay ----
            float* slog = smem;   // [128][64], col e ^ (m&31)
#pragma unroll
            for (int tp = 0; tp < 4; tp++) {
                const int m0 =
                    ((tp & 1) ? 4 * tg + 2 : 4 * tg) + ((tp & 2) ? 64 : 0);
                const int m1 = m0 + 1;
#pragma unroll
                for (int e = 0; e < 8; e++) {
                    const int ex = 8 * eg + e;
                    slog[m0 * 64 + (ex ^ (m0 & 31))] =
                        __uint_as_float((uint32_t)acc[tp][e]);
                    slog[m1 * 64 + (ex ^ (m1 & 31))] =
                        __uint_as_float((uint32_t)(acc[tp][e] >> 32));
                }
            }
            BAR_SYNC(JOINA, 128);   // scatter visible to all of group A

            // ---- per-token epilogue (identical math; bias already in) ----
            const int m = tid;                 // 0..127
            const int gtok = bm + m;
            const float cap =
                0.5f + 1.1f * ((float)t_arr[gtok >> 12] / 1000.0f);
            const int msw = m & 31;
            const float* row = slog + m * 64;

            float p[NE];
#pragma unroll
            for (int e = 0; e < NE; e++) p[e] = row[e ^ msw];

            float mx = -3.402823466e38f;
#pragma unroll 8
            for (int e = 0; e < NE; e++) mx = fmaxf(mx, p[e]);
            float s = 0.0f;
#pragma unroll 4
            for (int e = 0; e < NE; e++) {
                const float v = expf(p[e] - mx);
                s += v;
                p[e] = v;
            }
            const float inv = 1.0f / s;

            float summin = 0.0f, sumex = 0.0f;
#pragma unroll 8
            for (int e = 0; e < NE; e++) {
                const float q = 0.85f * (p[e] * inv) + (0.15f / 64.0f);
                p[e] = q;
                const float cc = fminf(q, cap);
                summin += cc;
                sumex += q - cc;
            }
            const float hs = fmaxf(64.0f * cap - summin, 1e-8f);
            const float scale = sumex / hs;

            float v1 = -1.0f, v2 = -1.0f;
            int i1 = 0, i2 = 0;
#pragma unroll 8
            for (int e = 0; e < NE; e++) {
                const float cc = fminf(p[e], cap);
                const float f = cc + scale * (cap - cc);
                if (f > v1)      { v2 = v1; i2 = i1; v1 = f; i1 = e; }
                else if (f > v2) { v2 = f; i2 = e; }
            }

            float* orow = out + (size_t)gtok * NE;
            const float4 z = make_float4(0.f, 0.f, 0.f, 0.f);
#pragma unroll
            for (int u = 0; u < 16; u++)
                reinterpret_cast<float4*>(orow)[u] = z;
            orow[i1] = v1;
            orow[i2] = v2;
        }
    }
}

extern "C" void kernel_launch(void* const* d_in, const int* in_sizes, int n_in,
                              void* d_out, int out_size)
{
    const float* tokens = (const float*)d_in[0];   // (16, 4096, 1024) f32
    const int*   t_arr  = (const int*)d_in[1];     // (16,) i32
    const float* Wg     = (const float*)d_in[2];   // (64, 1024) f32
    const float* bg     = (const float*)d_in[3];   // (64,) f32
    float*       out    = (float*)d_out;           // (16, 4096, 64) f32

    cudaFuncSetAttribute(router_ffma2_kernel,
                         cudaFuncAttributeMaxDynamicSharedMemorySize,
                         SMEM_FLOATS * 4);

    router_ffma2_kernel<<<NTOK / TILE_M, NTHREADS, SMEM_FLOATS * 4>>>(
        tokens, t_arr, Wg, bg, out);
}